// round 5
// baseline (speedup 1.0000x reference)
#include <cuda_runtime.h>
#include <cstdint>
#include <math.h>

#define BB 4
#define VV 2048
#define TT 12
#define HH 64
#define EE 32768
#define VT (BB*VV)            /* 8192 */
#define TOTK 27
#define KK (TOTK*HH + HH)     /* 1792 */
#define NCONV 7
#define VH (VT*HH)

// ================= helpers =================
__device__ __forceinline__ uint32_t smem_u32(const void* p) {
    uint32_t a;
    asm("{ .reg .u64 t; cvta.to.shared.u64 t, %1; cvt.u32.u64 %0, t; }" : "=r"(a) : "l"(p));
    return a;
}
__device__ __forceinline__ void cp16(uint32_t dst, const void* src) {
    asm volatile("cp.async.ca.shared.global [%0], [%1], 16;" :: "r"(dst), "l"(src));
}
#define CP_COMMIT() asm volatile("cp.async.commit_group;" ::: "memory")
#define CP_WAIT1()  asm volatile("cp.async.wait_group 1;" ::: "memory")
#define CP_WAIT0()  asm volatile("cp.async.wait_group 0;" ::: "memory")

__device__ __forceinline__ float to_tf32(float v) {
    uint32_t r;
    asm("cvt.rna.tf32.f32 %0, %1;" : "=r"(r) : "f"(v));
    return __uint_as_float(r);
}
// k-group permutation: logical j stored at ((j&3)<<1)|(j>>2); inverse below.
__device__ __forceinline__ int inv3(int s) { return (s & ~7) | ((s >> 1) & 3) | ((s & 1) << 2); }

// ================= persistent device scratch =================
__device__ __align__(256) float          g_Fv[VT * KK];          // K-permuted, tf32-rounded
__device__ __align__(256) float          g_Wt[NCONV * HH * KK];  // [perm conv][n][k-perm]
__device__ __align__(256) float          g_biasP[NCONV * HH];
__device__ __align__(256) float          g_basis[EE * 8];
__device__ __align__(256) unsigned short g_wis[EE * 8];
__device__ int            g_deg[VV];
__device__ float          g_deginv[VV];
__device__ int            g_csroff[VV + 1];
__device__ int            g_csredge[EE];
__device__ __align__(256) float g_h [VH];
__device__ __align__(256) float g_a [VH];
__device__ __align__(256) float g_ho[VH];
__device__ __align__(256) float g_hz[2 * VH];    // hr, zh
__device__ __align__(256) float g_xg[3 * VH];    // rx, zx, nx

// ---------------- pack (+ zero g_deg / g_h): conv perm {0,2,4,1,3,5,6}, K-perm, tf32 ----
__global__ void k_pack(const float* __restrict__ Wk, const float* __restrict__ Wroot,
                       const float* __restrict__ bias) {
    int idx = blockIdx.x * blockDim.x + threadIdx.x;
    if (idx < VV) g_deg[idx] = 0;
    if (idx < VH) g_h[idx] = 0.0f;
    if (idx >= NCONV * HH * KK) return;
    int k = idx % KK;                 // storage k
    int n = (idx / KK) & 63;
    int p = idx / (KK * HH);
    int kl = inv3(k);                 // logical k
    const int perm[7] = {0, 2, 4, 1, 3, 5, 6};
    int conv = perm[p];
    float v = (kl < TOTK * HH) ? Wk[(conv * TOTK * HH + kl) * HH + n]
                               : Wroot[(conv * HH + (kl - TOTK * HH)) * HH + n];
    g_Wt[idx] = to_tf32(v);
    if (k == 0) g_biasP[p * HH + n] = bias[conv * HH + n];
}

// ---------------- spline basis + degree histogram ----------------
__global__ void k_basis(const float* __restrict__ attr, const int* __restrict__ eidx) {
    int e = blockIdx.x * blockDim.x + threadIdx.x;
    if (e >= EE) return;
    float fr[3]; int lo[3];
    #pragma unroll
    for (int d = 0; d < 3; d++) {
        float u  = attr[e * 3 + d] * 2.0f;
        float fl = fminf(fmaxf(floorf(u), 0.0f), 1.0f);
        fr[d] = u - fl;
        lo[d] = (int)fl;
    }
    atomicAdd(&g_deg[eidx[EE + e]], 1);
    #pragma unroll
    for (int s = 0; s < 8; s++) {
        int b0 = s & 1, b1 = (s >> 1) & 1, b2 = (s >> 2) & 1;
        float b = (b0 ? fr[0] : 1.0f - fr[0])
                * (b1 ? fr[1] : 1.0f - fr[1])
                * (b2 ? fr[2] : 1.0f - fr[2]);
        int w = (lo[0] + b0) + 3 * (lo[1] + b1) + 9 * (lo[2] + b2);
        g_basis[e * 8 + s] = b;
        g_wis  [e * 8 + s] = (unsigned short)(w * HH);
    }
}

__global__ void k_scan() {
    __shared__ int sdeg[VV];
    __shared__ int soff[VV + 1];
    int tid = threadIdx.x;
    for (int v = tid; v < VV; v += blockDim.x) sdeg[v] = g_deg[v];
    __syncthreads();
    if (tid == 0) {
        int a = 0;
        for (int v = 0; v < VV; v++) { soff[v] = a; a += sdeg[v]; }
        soff[VV] = a;
    }
    __syncthreads();
    for (int v = tid; v < VV; v += blockDim.x) {
        g_csroff[v] = soff[v];
        g_deginv[v] = 1.0f / (float)max(sdeg[v], 1);
    }
    if (tid == 0) g_csroff[VV] = soff[VV];
}

__global__ void k_fill(const int* __restrict__ eidx) {
    int warp = (blockIdx.x * blockDim.x + threadIdx.x) >> 5;
    int lane = threadIdx.x & 31;
    if (warp >= VV) return;
    const int* dst = eidx + EE;
    int cnt = g_csroff[warp];
    for (int base = 0; base < EE; base += 32) {
        int d = dst[base + lane];
        unsigned m = __ballot_sync(0xFFFFFFFFu, d == warp);
        if (d == warp)
            g_csredge[cnt + __popc(m & ((1u << lane) - 1u))] = base + lane;
        cnt += __popc(m);
    }
}

// ---------------- scatter: Fv rows via CSR gather; batched slot loads (slots distinct) ----
__global__ void __launch_bounds__(256) k_scatter(const float* __restrict__ feat, int stride,
                                                 const int* __restrict__ eidx) {
    int c    = threadIdx.x;            // storage column
    int nsub = threadIdx.y;
    int node = blockIdx.x * 4 + nsub;
    int b = node >> 11;
    int v = node & (VV - 1);
    int cl = inv3(c);                  // logical channel feeding storage column c
    __shared__ float acc[4][TOTK * HH];
    float* ap = &acc[nsub][c];
    #pragma unroll
    for (int k = 0; k < TOTK; k++) ap[k * HH] = 0.0f;

    int i0 = g_csroff[v], i1 = g_csroff[v + 1];
    int base = b * VV;
    for (int ii = i0; ii < i1; ii++) {
        int e = g_csredge[ii];
        float4  bA = *(const float4*)&g_basis[e * 8];
        float4  bB = *(const float4*)&g_basis[e * 8 + 4];
        ushort4 wA = *(const ushort4*)&g_wis[e * 8];
        ushort4 wB = *(const ushort4*)&g_wis[e * 8 + 4];
        int src = eidx[e];
        float xs = feat[(base + src) * stride + cl];
        // slots within an edge are pairwise distinct: batch loads, then stores
        float v0 = ap[wA.x], v1 = ap[wA.y], v2 = ap[wA.z], v3 = ap[wA.w];
        float v4 = ap[wB.x], v5 = ap[wB.y], v6 = ap[wB.z], v7 = ap[wB.w];
        ap[wA.x] = fmaf(bA.x, xs, v0);
        ap[wA.y] = fmaf(bA.y, xs, v1);
        ap[wA.z] = fmaf(bA.z, xs, v2);
        ap[wA.w] = fmaf(bA.w, xs, v3);
        ap[wB.x] = fmaf(bB.x, xs, v4);
        ap[wB.y] = fmaf(bB.y, xs, v5);
        ap[wB.z] = fmaf(bB.z, xs, v6);
        ap[wB.w] = fmaf(bB.w, xs, v7);
    }
    float di = g_deginv[v];
    float* o = &g_Fv[node * KK + c];
    #pragma unroll
    for (int k = 0; k < TOTK; k++) o[k * HH] = to_tf32(ap[k * HH] * di);
    o[TOTK * HH] = to_tf32(feat[node * stride + cl]);
}

// ---------------- TF32 mma.sync GEMM, 3-stage cp.async, LDS.64 fragments ----------------
// Block 64x64, 128 thr (4 warps, 2x2, warp tile 32x32). gridDim.y = conv within group.
template <int EPI>
__global__ void __launch_bounds__(128) k_gemm(const float* __restrict__ Bw,
                                              const float* __restrict__ bias,
                                              const float* __restrict__ extra,
                                              float* __restrict__ out) {
    extern __shared__ float smem[];
    float (*As)[64][36] = reinterpret_cast<float (*)[64][36]>(smem);
    float (*Bs)[64][36] = reinterpret_cast<float (*)[64][36]>(smem + 3 * 64 * 36);

    const int tid  = threadIdx.x;
    const int m0   = blockIdx.x * 64;
    const int grp  = blockIdx.y;
    Bw   += grp * 64 * KK;
    bias += grp * 64;
    out  += grp * VH;

    const int lane = tid & 31, wid = tid >> 5;
    const int wm = (wid & 1) * 32, wn = (wid >> 1) * 32;
    const int g  = lane >> 2,  tq = lane & 3;

    float c[2][4][4];
    #pragma unroll
    for (int mt = 0; mt < 2; mt++)
        #pragma unroll
        for (int nt = 0; nt < 4; nt++)
            #pragma unroll
            for (int i = 0; i < 4; i++) c[mt][nt][i] = 0.0f;

    const int arow = tid >> 1;
    const int as0  = (tid & 1) * 4;
    const float* Ag = &g_Fv[(uint64_t)(m0 + arow) * KK];
    const float* Bg = &Bw[(uint64_t)arow * KK];
    const uint32_t sA = smem_u32(&As[0][0][0]);
    const uint32_t sB = smem_u32(&Bs[0][0][0]);

    auto load_tiles = [&](int kc, int st) {
        uint32_t da = sA + (uint32_t)st * (64 * 36 * 4) + (uint32_t)arow * 144;
        uint32_t db = sB + (uint32_t)st * (64 * 36 * 4) + (uint32_t)arow * 144;
        const float* ga = Ag + kc * 32;
        const float* gb = Bg + kc * 32;
        #pragma unroll
        for (int i = 0; i < 4; i++) {
            int s = as0 + i;
            cp16(da + s * 16, ga + s * 4);
            cp16(db + s * 16, gb + s * 4);
        }
    };

    const int NCH = KK / 32;   // 56
    load_tiles(0, 0); CP_COMMIT();
    load_tiles(1, 1); CP_COMMIT();

    for (int ck = 0; ck < NCH; ck++) {
        if (ck < NCH - 1) CP_WAIT1(); else CP_WAIT0();
        __syncthreads();
        if (ck + 2 < NCH) { load_tiles(ck + 2, (ck + 2) % 3); CP_COMMIT(); }
        const int buf = ck % 3;
        #pragma unroll
        for (int s8 = 0; s8 < 4; s8++) {
            const int k8 = s8 * 8;
            uint32_t a[2][4], b[4][2];
            #pragma unroll
            for (int mt = 0; mt < 2; mt++) {
                int r0 = wm + mt * 16 + g;
                float2 p = *(const float2*)&As[buf][r0    ][k8 + 2 * tq];
                float2 q = *(const float2*)&As[buf][r0 + 8][k8 + 2 * tq];
                a[mt][0] = __float_as_uint(p.x); a[mt][2] = __float_as_uint(p.y);
                a[mt][1] = __float_as_uint(q.x); a[mt][3] = __float_as_uint(q.y);
            }
            #pragma unroll
            for (int nt = 0; nt < 4; nt++) {
                int br = wn + nt * 8 + g;
                float2 r = *(const float2*)&Bs[buf][br][k8 + 2 * tq];
                b[nt][0] = __float_as_uint(r.x); b[nt][1] = __float_as_uint(r.y);
            }
            #pragma unroll
            for (int mt = 0; mt < 2; mt++)
                #pragma unroll
                for (int nt = 0; nt < 4; nt++) {
                    float* cc = c[mt][nt];
                    asm volatile(
                        "mma.sync.aligned.m16n8k8.row.col.f32.tf32.tf32.f32 "
                        "{%0,%1,%2,%3},{%4,%5,%6,%7},{%8,%9},{%0,%1,%2,%3};"
                        : "+f"(cc[0]), "+f"(cc[1]), "+f"(cc[2]), "+f"(cc[3])
                        : "r"(a[mt][0]), "r"(a[mt][1]), "r"(a[mt][2]), "r"(a[mt][3]),
                          "r"(b[nt][0]), "r"(b[nt][1]));
                }
        }
    }

    // epilogue: bias + activation (+extra), float2 stores (N-dim is unpermuted)
    #pragma unroll
    for (int mt = 0; mt < 2; mt++) {
        #pragma unroll
        for (int nt = 0; nt < 4; nt++) {
            int col = wn + nt * 8 + 2 * tq;
            float b0 = bias[col], b1 = bias[col + 1];
            #pragma unroll
            for (int half = 0; half < 2; half++) {
                int row = m0 + wm + mt * 16 + g + half * 8;
                float v0 = c[mt][nt][half * 2 + 0] + b0;
                float v1 = c[mt][nt][half * 2 + 1] + b1;
                if (EPI == 1) {
                    v0 = (v0 > 0.0f) ? v0 : (expf(v0) - 1.0f);
                    v1 = (v1 > 0.0f) ? v1 : (expf(v1) - 1.0f);
                }
                int o = row * 64 + col;
                if (EPI == 2) {
                    float2 e2 = *(const float2*)&extra[o];
                    v0 = e2.x + tanhf(v0);
                    v1 = e2.y + tanhf(v1);
                }
                float2 st = make_float2(v0, v1);
                *(float2*)&out[o] = st;
            }
        }
    }
}

// ---------------- GRU gates + output ----------------
__global__ void k_gates(float* __restrict__ out, int t) {
    int i = blockIdx.x * blockDim.x + threadIdx.x;
    float rx = g_xg[i], zx = g_xg[VH + i], nx = g_xg[2 * VH + i];
    float hr = g_hz[i], zh = g_hz[VH + i], ho = g_ho[i];
    float r = 1.0f / (1.0f + expf(-(rx + hr)));
    float z = 1.0f / (1.0f + expf(-(zx + zh)));
    float n = tanhf(nx + r * hr);
    float h = (1.0f - z) * n + z * ho;
    g_h[i] = h;
    int node = i >> 6, c = i & 63;
    out[(node * TT + t) * HH + c] = h;
}

// ---------------- launch ----------------
extern "C" void kernel_launch(void* const* d_in, const int* in_sizes, int n_in,
                              void* d_out, int out_size) {
    const float* x     = (const float*)d_in[0];
    const float* attr  = (const float*)d_in[1];
    const float* Wk    = (const float*)d_in[2];
    const float* Wroot = (const float*)d_in[3];
    const float* bias  = (const float*)d_in[4];
    const int*   eidx  = (const int*)d_in[5];
    float*       out   = (float*)d_out;

    float *pWt, *pBias, *pH, *pA, *pHO, *pHZ, *pXG;
    cudaGetSymbolAddress((void**)&pWt,   g_Wt);
    cudaGetSymbolAddress((void**)&pBias, g_biasP);
    cudaGetSymbolAddress((void**)&pH,    g_h);
    cudaGetSymbolAddress((void**)&pA,    g_a);
    cudaGetSymbolAddress((void**)&pHO,   g_ho);
    cudaGetSymbolAddress((void**)&pHZ,   g_hz);
    cudaGetSymbolAddress((void**)&pXG,   g_xg);

    const int SMEM = 3 * 2 * 64 * 36 * 4;   // 55296 B
    cudaFuncSetAttribute(k_gemm<0>, cudaFuncAttributeMaxDynamicSharedMemorySize, SMEM);
    cudaFuncSetAttribute(k_gemm<1>, cudaFuncAttributeMaxDynamicSharedMemorySize, SMEM);
    cudaFuncSetAttribute(k_gemm<2>, cudaFuncAttributeMaxDynamicSharedMemorySize, SMEM);

    // launch order keeps k_gemm<1> as the 6th kernel => ncu (-s 5 -c 1) captures it
    k_pack <<<(NCONV * HH * KK + 255) / 256, 256>>>(Wk, Wroot, bias);
    k_basis<<<EE / 256, 256>>>(attr, eidx);
    k_scan <<<1, 1024>>>();
    k_fill <<<VV / 8, 256>>>(eidx);

    const dim3 sblk(64, 4);
    const int  HK = HH * KK;
    const dim3 g1(VT / 64, 1), g2(VT / 64, 2), g3(VT / 64, 3);

    for (int t = 0; t < TT; t++) {
        // ODE: a = elu(conv5(h)) ; ho = h + tanh(conv6(a))
        k_scatter<<<VT / 4, sblk>>>(pH, HH, eidx);
        k_gemm<1><<<g1, 128, SMEM>>>(pWt + 5 * HK, pBias + 5 * HH, nullptr, pA);
        k_scatter<<<VT / 4, sblk>>>(pA, HH, eidx);
        k_gemm<2><<<g1, 128, SMEM>>>(pWt + 6 * HK, pBias + 6 * HH, pH, pHO);
        // GRU h-side fused: [hr | zh] = conv{1,3}(ho)
        k_scatter<<<VT / 4, sblk>>>(pHO, HH, eidx);
        k_gemm<0><<<g2, 128, SMEM>>>(pWt + 3 * HK, pBias + 3 * HH, nullptr, pHZ);
        // GRU x-side fused: [rx | zx | nx] = conv{0,2,4}(x_t)
        k_scatter<<<VT / 4, sblk>>>(x + t * HH, TT * HH, eidx);
        k_gemm<0><<<g3, 128, SMEM>>>(pWt, pBias, nullptr, pXG);
        // gates + output
        k_gates<<<VH / 256, 256>>>(out, t);
    }
}

// round 6
// speedup vs baseline: 1.1996x; 1.1996x over previous
#include <cuda_runtime.h>
#include <cstdint>
#include <math.h>

#define BB 4
#define VV 2048
#define TT 12
#define HH 64
#define EE 32768
#define VT (BB*VV)            /* 8192 */
#define TOTK 27
#define KK (TOTK*HH + HH)     /* 1792 */
#define NCONV 7
#define VH (VT*HH)

// ================= helpers =================
__device__ __forceinline__ uint32_t smem_u32(const void* p) {
    uint32_t a;
    asm("{ .reg .u64 t; cvta.to.shared.u64 t, %1; cvt.u32.u64 %0, t; }" : "=r"(a) : "l"(p));
    return a;
}
__device__ __forceinline__ void cp16(uint32_t dst, const void* src) {
    asm volatile("cp.async.ca.shared.global [%0], [%1], 16;" :: "r"(dst), "l"(src));
}
#define CP_COMMIT() asm volatile("cp.async.commit_group;" ::: "memory")
#define CP_WAIT0()  asm volatile("cp.async.wait_group 0;" ::: "memory")

__device__ __forceinline__ float to_tf32(float v) {
    uint32_t r;
    asm("cvt.rna.tf32.f32 %0, %1;" : "=r"(r) : "f"(v));
    return __uint_as_float(r);
}

// ================= persistent device scratch =================
__device__ __align__(256) float          g_Fv[VT * KK];          // tf32-rounded
__device__ __align__(256) float          g_Wt[NCONV * HH * KK];  // [perm conv][n][k]
__device__ __align__(256) float          g_biasP[NCONV * HH];
__device__ __align__(256) float          g_basis[EE * 8];
__device__ __align__(256) unsigned short g_wis[EE * 8];
// CSR-ordered edge tables (chain-free scatter)
__device__ __align__(256) float          g_basisC[EE * 8];
__device__ __align__(256) unsigned short g_wisC[EE * 8];
__device__ __align__(256) int            g_srcC[EE];
__device__ int            g_deg[VV];
__device__ float          g_deginv[VV];
__device__ int            g_csroff[VV + 1];
__device__ int            g_csredge[EE];
__device__ __align__(256) float g_h [VH];
__device__ __align__(256) float g_a [VH];
__device__ __align__(256) float g_ho[VH];
__device__ __align__(256) float g_hz[2 * VH];    // hr, zh
__device__ __align__(256) float g_xg[3 * VH];    // rx, zx, nx

// ---------------- pack (+ zero g_deg/g_h): conv perm {0,2,4,1,3,5,6}, tf32 ----
__global__ void k_pack(const float* __restrict__ Wk, const float* __restrict__ Wroot,
                       const float* __restrict__ bias) {
    int idx = blockIdx.x * blockDim.x + threadIdx.x;
    if (idx < VV) g_deg[idx] = 0;
    if (idx < VH) g_h[idx] = 0.0f;
    if (idx >= NCONV * HH * KK) return;
    int k = idx % KK;
    int n = (idx / KK) & 63;
    int p = idx / (KK * HH);
    const int perm[7] = {0, 2, 4, 1, 3, 5, 6};
    int conv = perm[p];
    float v = (k < TOTK * HH) ? Wk[(conv * TOTK * HH + k) * HH + n]
                              : Wroot[(conv * HH + (k - TOTK * HH)) * HH + n];
    g_Wt[idx] = to_tf32(v);
    if (k == 0) g_biasP[p * HH + n] = bias[conv * HH + n];
}

// ---------------- spline basis + degree histogram ----------------
__global__ void k_basis(const float* __restrict__ attr, const int* __restrict__ eidx) {
    int e = blockIdx.x * blockDim.x + threadIdx.x;
    if (e >= EE) return;
    float fr[3]; int lo[3];
    #pragma unroll
    for (int d = 0; d < 3; d++) {
        float u  = attr[e * 3 + d] * 2.0f;
        float fl = fminf(fmaxf(floorf(u), 0.0f), 1.0f);
        fr[d] = u - fl;
        lo[d] = (int)fl;
    }
    atomicAdd(&g_deg[eidx[EE + e]], 1);
    #pragma unroll
    for (int s = 0; s < 8; s++) {
        int b0 = s & 1, b1 = (s >> 1) & 1, b2 = (s >> 2) & 1;
        float b = (b0 ? fr[0] : 1.0f - fr[0])
                * (b1 ? fr[1] : 1.0f - fr[1])
                * (b2 ? fr[2] : 1.0f - fr[2]);
        int w = (lo[0] + b0) + 3 * (lo[1] + b1) + 9 * (lo[2] + b2);
        g_basis[e * 8 + s] = b;
        g_wis  [e * 8 + s] = (unsigned short)(w * HH);
    }
}

__global__ void k_scan() {
    __shared__ int sdeg[VV];
    __shared__ int soff[VV + 1];
    int tid = threadIdx.x;
    for (int v = tid; v < VV; v += blockDim.x) sdeg[v] = g_deg[v];
    __syncthreads();
    if (tid == 0) {
        int a = 0;
        for (int v = 0; v < VV; v++) { soff[v] = a; a += sdeg[v]; }
        soff[VV] = a;
    }
    __syncthreads();
    for (int v = tid; v < VV; v += blockDim.x) {
        g_csroff[v] = soff[v];
        g_deginv[v] = 1.0f / (float)max(sdeg[v], 1);
    }
    if (tid == 0) g_csroff[VV] = soff[VV];
}

__global__ void k_fill(const int* __restrict__ eidx) {
    int warp = (blockIdx.x * blockDim.x + threadIdx.x) >> 5;
    int lane = threadIdx.x & 31;
    if (warp >= VV) return;
    const int* dst = eidx + EE;
    int cnt = g_csroff[warp];
    for (int base = 0; base < EE; base += 32) {
        int d = dst[base + lane];
        unsigned m = __ballot_sync(0xFFFFFFFFu, d == warp);
        if (d == warp)
            g_csredge[cnt + __popc(m & ((1u << lane) - 1u))] = base + lane;
        cnt += __popc(m);
    }
}

// ---------------- one-time: reorder edge tables into CSR order ----------------
__global__ void k_csrtab(const int* __restrict__ eidx) {
    int ii = blockIdx.x * blockDim.x + threadIdx.x;
    if (ii >= EE) return;
    int e = g_csredge[ii];
    g_srcC[ii] = eidx[e];
    *(float4*)&g_basisC[ii * 8]     = *(const float4*)&g_basis[e * 8];
    *(float4*)&g_basisC[ii * 8 + 4] = *(const float4*)&g_basis[e * 8 + 4];
    *(ushort4*)&g_wisC[ii * 8]      = *(const ushort4*)&g_wis[e * 8];
    *(ushort4*)&g_wisC[ii * 8 + 4]  = *(const ushort4*)&g_wis[e * 8 + 4];
}

// ---------------- scatter: CSR-ordered tables, single-gather inner loop ----------------
__global__ void __launch_bounds__(256) k_scatter(const float* __restrict__ feat, int stride,
                                                 const int* __restrict__ eidx) {
    int c    = threadIdx.x;            // 0..63 channel
    int nsub = threadIdx.y;            // 0..3
    int node = blockIdx.x * 4 + nsub;
    int b = node >> 11;
    int v = node & (VV - 1);
    __shared__ float acc[4][TOTK * HH];
    float* ap = &acc[nsub][c];
    #pragma unroll
    for (int k = 0; k < TOTK; k++) ap[k * HH] = 0.0f;

    int i0 = g_csroff[v], i1 = g_csroff[v + 1];
    int base = b * VV;
    for (int ii = i0; ii < i1; ii++) {
        // tables are sequential + warp-uniform (broadcast); only feat is a gather
        float4  bA = *(const float4*)&g_basisC[ii * 8];
        float4  bB = *(const float4*)&g_basisC[ii * 8 + 4];
        ushort4 wA = *(const ushort4*)&g_wisC[ii * 8];
        ushort4 wB = *(const ushort4*)&g_wisC[ii * 8 + 4];
        int src = g_srcC[ii];
        float xs = feat[(base + src) * stride + c];
        // slots within an edge are pairwise distinct: batch loads, then stores
        float v0 = ap[wA.x], v1 = ap[wA.y], v2 = ap[wA.z], v3 = ap[wA.w];
        float v4 = ap[wB.x], v5 = ap[wB.y], v6 = ap[wB.z], v7 = ap[wB.w];
        ap[wA.x] = fmaf(bA.x, xs, v0);
        ap[wA.y] = fmaf(bA.y, xs, v1);
        ap[wA.z] = fmaf(bA.z, xs, v2);
        ap[wA.w] = fmaf(bA.w, xs, v3);
        ap[wB.x] = fmaf(bB.x, xs, v4);
        ap[wB.y] = fmaf(bB.y, xs, v5);
        ap[wB.z] = fmaf(bB.z, xs, v6);
        ap[wB.w] = fmaf(bB.w, xs, v7);
    }
    float di = g_deginv[v];
    float* o = &g_Fv[node * KK + c];
    #pragma unroll
    for (int k = 0; k < TOTK; k++) o[k * HH] = to_tf32(ap[k * HH] * di);
    o[TOTK * HH] = to_tf32(feat[node * stride + c]);
}

// ---------------- TF32 mma.sync GEMM (R4 core), NG output groups per A pass ----------------
// Block 64(M) x 64(N) per group; 128 thr (4 warps 2x2, warp tile 32x32).
// EPI: 0 plain(+bias), 1 elu(+bias), 2 extra + tanh(+bias). EPI!=0 only with NG==1.
template <int NG, int EPI>
__global__ void __launch_bounds__(128) k_gemm(const float* __restrict__ Bw,
                                              const float* __restrict__ bias,
                                              const float* __restrict__ extra,
                                              float* __restrict__ out) {
    extern __shared__ float smem[];
    float (*As)[64][36]      = reinterpret_cast<float (*)[64][36]>(smem);
    float (*Bs)[NG * 64][36] = reinterpret_cast<float (*)[NG * 64][36]>(smem + 2 * 64 * 36);

    const int tid  = threadIdx.x;
    const int m0   = blockIdx.x * 64;
    const int lane = tid & 31, wid = tid >> 5;
    const int wm = (wid & 1) * 32, wn = (wid >> 1) * 32;
    const int g  = lane >> 2,  tq = lane & 3;

    float c[NG][2][4][4];
    #pragma unroll
    for (int gg = 0; gg < NG; gg++)
        #pragma unroll
        for (int mt = 0; mt < 2; mt++)
            #pragma unroll
            for (int nt = 0; nt < 4; nt++)
                #pragma unroll
                for (int i = 0; i < 4; i++) c[gg][mt][nt][i] = 0.0f;

    const int arow = tid >> 1;
    const int as0  = (tid & 1) * 4;
    const float* Ag = &g_Fv[(uint64_t)(m0 + arow) * KK];
    const uint32_t sA = smem_u32(&As[0][0][0]);
    const uint32_t sB = smem_u32(&Bs[0][0][0]);

    auto load_tiles = [&](int kc, int st) {
        uint32_t da = sA + (uint32_t)st * (64 * 36 * 4) + (uint32_t)arow * 144;
        const float* ga = Ag + kc * 32;
        #pragma unroll
        for (int i = 0; i < 4; i++) {
            int s = as0 + i;
            cp16(da + s * 16, ga + s * 4);
        }
        #pragma unroll
        for (int gg = 0; gg < NG; gg++) {
            uint32_t db = sB + (uint32_t)st * (NG * 64 * 36 * 4)
                        + (uint32_t)(gg * 64 + arow) * 144;
            const float* gb = &Bw[(uint64_t)(gg * 64 + arow) * KK + kc * 32];
            #pragma unroll
            for (int i = 0; i < 4; i++) {
                int s = as0 + i;
                cp16(db + s * 16, gb + s * 4);
            }
        }
    };

    const int NCH = KK / 32;   // 56
    load_tiles(0, 0);
    CP_COMMIT();

    for (int ck = 0; ck < NCH; ck++) {
        CP_WAIT0();
        __syncthreads();
        if (ck + 1 < NCH) { load_tiles(ck + 1, (ck + 1) & 1); CP_COMMIT(); }
        const int buf = ck & 1;
        #pragma unroll
        for (int s8 = 0; s8 < 4; s8++) {
            const int k8 = s8 * 8;
            uint32_t a[2][4];
            #pragma unroll
            for (int mt = 0; mt < 2; mt++) {
                int r0 = wm + mt * 16 + g;
                a[mt][0] = __float_as_uint(As[buf][r0    ][k8 + tq]);
                a[mt][1] = __float_as_uint(As[buf][r0 + 8][k8 + tq]);
                a[mt][2] = __float_as_uint(As[buf][r0    ][k8 + tq + 4]);
                a[mt][3] = __float_as_uint(As[buf][r0 + 8][k8 + tq + 4]);
            }
            #pragma unroll
            for (int gg = 0; gg < NG; gg++) {
                uint32_t b[4][2];
                #pragma unroll
                for (int nt = 0; nt < 4; nt++) {
                    int br = gg * 64 + wn + nt * 8 + g;
                    b[nt][0] = __float_as_uint(Bs[buf][br][k8 + tq]);
                    b[nt][1] = __float_as_uint(Bs[buf][br][k8 + tq + 4]);
                }
                #pragma unroll
                for (int mt = 0; mt < 2; mt++)
                    #pragma unroll
                    for (int nt = 0; nt < 4; nt++) {
                        float* cc = c[gg][mt][nt];
                        asm volatile(
                            "mma.sync.aligned.m16n8k8.row.col.f32.tf32.tf32.f32 "
                            "{%0,%1,%2,%3},{%4,%5,%6,%7},{%8,%9},{%0,%1,%2,%3};"
                            : "+f"(cc[0]), "+f"(cc[1]), "+f"(cc[2]), "+f"(cc[3])
                            : "r"(a[mt][0]), "r"(a[mt][1]), "r"(a[mt][2]), "r"(a[mt][3]),
                              "r"(b[nt][0]), "r"(b[nt][1]));
                    }
            }
        }
        __syncthreads();
    }

    // epilogue
    #pragma unroll
    for (int gg = 0; gg < NG; gg++) {
        float* outg = out + gg * VH;
        const float* biasg = bias + gg * 64;
        #pragma unroll
        for (int mt = 0; mt < 2; mt++) {
            #pragma unroll
            for (int nt = 0; nt < 4; nt++) {
                int col = wn + nt * 8 + 2 * tq;
                float b0 = biasg[col], b1 = biasg[col + 1];
                #pragma unroll
                for (int half = 0; half < 2; half++) {
                    int row = m0 + wm + mt * 16 + g + half * 8;
                    float v0 = c[gg][mt][nt][half * 2 + 0] + b0;
                    float v1 = c[gg][mt][nt][half * 2 + 1] + b1;
                    if (EPI == 1) {
                        v0 = (v0 > 0.0f) ? v0 : (expf(v0) - 1.0f);
                        v1 = (v1 > 0.0f) ? v1 : (expf(v1) - 1.0f);
                    }
                    int o = row * 64 + col;
                    if (EPI == 2) {
                        float2 e2 = *(const float2*)&extra[o];
                        v0 = e2.x + tanhf(v0);
                        v1 = e2.y + tanhf(v1);
                    }
                    *(float2*)&outg[o] = make_float2(v0, v1);
                }
            }
        }
    }
}

// ---------------- GRU gates + output ----------------
__global__ void k_gates(float* __restrict__ out, int t) {
    int i = blockIdx.x * blockDim.x + threadIdx.x;
    float rx = g_xg[i], zx = g_xg[VH + i], nx = g_xg[2 * VH + i];
    float hr = g_hz[i], zh = g_hz[VH + i], ho = g_ho[i];
    float r = 1.0f / (1.0f + expf(-(rx + hr)));
    float z = 1.0f / (1.0f + expf(-(zx + zh)));
    float n = tanhf(nx + r * hr);
    float h = (1.0f - z) * n + z * ho;
    g_h[i] = h;
    int node = i >> 6, c = i & 63;
    out[(node * TT + t) * HH + c] = h;
}

// ---------------- launch ----------------
extern "C" void kernel_launch(void* const* d_in, const int* in_sizes, int n_in,
                              void* d_out, int out_size) {
    const float* x     = (const float*)d_in[0];
    const float* attr  = (const float*)d_in[1];
    const float* Wk    = (const float*)d_in[2];
    const float* Wroot = (const float*)d_in[3];
    const float* bias  = (const float*)d_in[4];
    const int*   eidx  = (const int*)d_in[5];
    float*       out   = (float*)d_out;

    float *pWt, *pBias, *pH, *pA, *pHO, *pHZ, *pXG;
    cudaGetSymbolAddress((void**)&pWt,   g_Wt);
    cudaGetSymbolAddress((void**)&pBias, g_biasP);
    cudaGetSymbolAddress((void**)&pH,    g_h);
    cudaGetSymbolAddress((void**)&pA,    g_a);
    cudaGetSymbolAddress((void**)&pHO,   g_ho);
    cudaGetSymbolAddress((void**)&pHZ,   g_hz);
    cudaGetSymbolAddress((void**)&pXG,   g_xg);

    const int SM1 = 18432 * 2;   // NG=1
    const int SM2 = 18432 * 3;   // NG=2
    const int SM3 = 18432 * 4;   // NG=3
    cudaFuncSetAttribute(k_gemm<1, 1>, cudaFuncAttributeMaxDynamicSharedMemorySize, SM1);
    cudaFuncSetAttribute(k_gemm<1, 2>, cudaFuncAttributeMaxDynamicSharedMemorySize, SM1);
    cudaFuncSetAttribute(k_gemm<2, 0>, cudaFuncAttributeMaxDynamicSharedMemorySize, SM2);
    cudaFuncSetAttribute(k_gemm<3, 0>, cudaFuncAttributeMaxDynamicSharedMemorySize, SM3);

    k_pack  <<<(NCONV * HH * KK + 255) / 256, 256>>>(Wk, Wroot, bias);
    k_basis <<<EE / 256, 256>>>(attr, eidx);
    k_scan  <<<1, 1024>>>();
    k_fill  <<<VV / 8, 256>>>(eidx);
    k_csrtab<<<EE / 256, 256>>>(eidx);

    const dim3 sblk(64, 4);
    const int  HK = HH * KK;
    const int  GG = VT / 64;     // 128

    for (int t = 0; t < TT; t++) {
        // ODE: a = elu(conv5(h)) ; ho = h + tanh(conv6(a))
        k_scatter<<<VT / 4, sblk>>>(pH, HH, eidx);
        k_gemm<1, 1><<<GG, 128, SM1>>>(pWt + 5 * HK, pBias + 5 * HH, nullptr, pA);
        k_scatter<<<VT / 4, sblk>>>(pA, HH, eidx);
        k_gemm<1, 2><<<GG, 128, SM1>>>(pWt + 6 * HK, pBias + 6 * HH, pH, pHO);
        // GRU h-side fused: [hr | zh] = conv{1,3}(ho)
        k_scatter<<<VT / 4, sblk>>>(pHO, HH, eidx);
        k_gemm<2, 0><<<GG, 128, SM2>>>(pWt + 3 * HK, pBias + 3 * HH, nullptr, pHZ);
        // GRU x-side fused: [rx | zx | nx] = conv{0,2,4}(x_t)
        k_scatter<<<VT / 4, sblk>>>(x + t * HH, TT * HH, eidx);
        k_gemm<3, 0><<<GG, 128, SM3>>>(pWt, pBias, nullptr, pXG);
        // gates + output
        k_gates<<<VH / 256, 256>>>(out, t);
    }
}

// round 7
// speedup vs baseline: 1.6885x; 1.4075x over previous
#include <cuda_runtime.h>
#include <cuda_fp16.h>
#include <cstdint>
#include <math.h>

#define BB 4
#define VV 2048
#define TT 12
#define HH 64
#define EE 32768
#define VT (BB*VV)            /* 8192 */
#define TOTK 27
#define KK (TOTK*HH + HH)     /* 1792 */
#define NCONV 7
#define VH (VT*HH)

// ================= helpers =================
__device__ __forceinline__ uint32_t smem_u32(const void* p) {
    uint32_t a;
    asm("{ .reg .u64 t; cvta.to.shared.u64 t, %1; cvt.u32.u64 %0, t; }" : "=r"(a) : "l"(p));
    return a;
}
__device__ __forceinline__ void cp16(uint32_t dst, const void* src) {
    asm volatile("cp.async.ca.shared.global [%0], [%1], 16;" :: "r"(dst), "l"(src));
}
#define CP_COMMIT() asm volatile("cp.async.commit_group;" ::: "memory")
#define CP_WAIT0()  asm volatile("cp.async.wait_group 0;" ::: "memory")

// ================= persistent device scratch =================
__device__ __align__(256) __half          g_FvH[VT * KK];         // 29.4 MB, fp16
__device__ __align__(256) __half          g_WtH[NCONV * HH * KK]; // [perm conv][n][k], fp16
__device__ __align__(256) float           g_biasP[NCONV * HH];
__device__ __align__(256) float           g_basis[EE * 8];
__device__ __align__(256) unsigned short  g_wis[EE * 8];
// CSR-ordered edge tables (chain-free scatter)
__device__ __align__(256) float           g_basisC[EE * 8];
__device__ __align__(256) unsigned short  g_wisC[EE * 8];
__device__ __align__(256) int             g_srcC[EE];
__device__ float          g_deginv[VV];
__device__ int            g_csroff[VV + 1];
__device__ __align__(256) float g_h [VH];
__device__ __align__(256) float g_a [VH];
__device__ __align__(256) float g_ho[VH];
__device__ __align__(256) float g_hz[2 * VH];    // hr, zh
__device__ __align__(256) float g_xg[3 * VH];    // rx, zx, nx

// ---------------- prep: weight pack (fp16) + spline basis + zero h ----------------
__global__ void k_prep(const float* __restrict__ Wk, const float* __restrict__ Wroot,
                       const float* __restrict__ bias, const float* __restrict__ attr) {
    int idx = blockIdx.x * blockDim.x + threadIdx.x;
    if (idx < VH) g_h[idx] = 0.0f;
    if (idx < EE) {
        int e = idx;
        float fr[3]; int lo[3];
        #pragma unroll
        for (int d = 0; d < 3; d++) {
            float u  = attr[e * 3 + d] * 2.0f;
            float fl = fminf(fmaxf(floorf(u), 0.0f), 1.0f);
            fr[d] = u - fl;
            lo[d] = (int)fl;
        }
        #pragma unroll
        for (int s = 0; s < 8; s++) {
            int b0 = s & 1, b1 = (s >> 1) & 1, b2 = (s >> 2) & 1;
            float b = (b0 ? fr[0] : 1.0f - fr[0])
                    * (b1 ? fr[1] : 1.0f - fr[1])
                    * (b2 ? fr[2] : 1.0f - fr[2]);
            int w = (lo[0] + b0) + 3 * (lo[1] + b1) + 9 * (lo[2] + b2);
            g_basis[e * 8 + s] = b;
            g_wis  [e * 8 + s] = (unsigned short)(w * HH);
        }
    }
    if (idx >= NCONV * HH * KK) return;
    int k = idx % KK;
    int n = (idx / KK) & 63;
    int p = idx / (KK * HH);
    const int perm[7] = {0, 2, 4, 1, 3, 5, 6};
    int conv = perm[p];
    float v = (k < TOTK * HH) ? Wk[(conv * TOTK * HH + k) * HH + n]
                              : Wroot[(conv * HH + (k - TOTK * HH)) * HH + n];
    g_WtH[idx] = __float2half(v);
    if (k == 0) g_biasP[p * HH + n] = bias[conv * HH + n];
}

// ---------------- degree histogram + exclusive scan (single block) ----------------
__global__ void k_scan(const int* __restrict__ eidx) {
    __shared__ int sdeg[VV];
    __shared__ int soff[VV + 1];
    int tid = threadIdx.x;
    for (int v = tid; v < VV; v += blockDim.x) sdeg[v] = 0;
    __syncthreads();
    const int* dst = eidx + EE;
    for (int e = tid; e < EE; e += blockDim.x) atomicAdd(&sdeg[dst[e]], 1);
    __syncthreads();
    if (tid == 0) {
        int a = 0;
        for (int v = 0; v < VV; v++) { soff[v] = a; a += sdeg[v]; }
        soff[VV] = a;
    }
    __syncthreads();
    for (int v = tid; v < VV; v += blockDim.x) {
        g_csroff[v] = soff[v];
        g_deginv[v] = 1.0f / (float)max(sdeg[v], 1);
    }
    if (tid == 0) g_csroff[VV] = soff[VV];
}

// ---------------- CSR fill (ballot-ordered, deterministic) + direct C-table build ----
__global__ void k_fill(const int* __restrict__ eidx) {
    int warp = (blockIdx.x * blockDim.x + threadIdx.x) >> 5;
    int lane = threadIdx.x & 31;
    if (warp >= VV) return;
    const int* dst = eidx + EE;
    int cnt = g_csroff[warp];
    for (int base = 0; base < EE; base += 32) {
        int d = dst[base + lane];
        unsigned m = __ballot_sync(0xFFFFFFFFu, d == warp);
        if (d == warp) {
            int pos = cnt + __popc(m & ((1u << lane) - 1u));
            int e = base + lane;
            g_srcC[pos] = eidx[e];
            *(float4*)&g_basisC[pos * 8]     = *(const float4*)&g_basis[e * 8];
            *(float4*)&g_basisC[pos * 8 + 4] = *(const float4*)&g_basis[e * 8 + 4];
            *(ushort4*)&g_wisC[pos * 8]      = *(const ushort4*)&g_wis[e * 8];
            *(ushort4*)&g_wisC[pos * 8 + 4]  = *(const ushort4*)&g_wis[e * 8 + 4];
        }
        cnt += __popc(m);
    }
}

// ---------------- scatter: CSR-ordered tables, single-gather inner loop, fp16 out ----
__global__ void __launch_bounds__(256) k_scatter(const float* __restrict__ feat, int stride) {
    int c    = threadIdx.x;            // 0..63 channel
    int nsub = threadIdx.y;            // 0..3
    int node = blockIdx.x * 4 + nsub;
    int b = node >> 11;
    int v = node & (VV - 1);
    __shared__ float acc[4][TOTK * HH];
    float* ap = &acc[nsub][c];
    #pragma unroll
    for (int k = 0; k < TOTK; k++) ap[k * HH] = 0.0f;

    int i0 = g_csroff[v], i1 = g_csroff[v + 1];
    int base = b * VV;
    for (int ii = i0; ii < i1; ii++) {
        float4  bA = *(const float4*)&g_basisC[ii * 8];
        float4  bB = *(const float4*)&g_basisC[ii * 8 + 4];
        ushort4 wA = *(const ushort4*)&g_wisC[ii * 8];
        ushort4 wB = *(const ushort4*)&g_wisC[ii * 8 + 4];
        int src = g_srcC[ii];
        float xs = feat[(base + src) * stride + c];
        float v0 = ap[wA.x], v1 = ap[wA.y], v2 = ap[wA.z], v3 = ap[wA.w];
        float v4 = ap[wB.x], v5 = ap[wB.y], v6 = ap[wB.z], v7 = ap[wB.w];
        ap[wA.x] = fmaf(bA.x, xs, v0);
        ap[wA.y] = fmaf(bA.y, xs, v1);
        ap[wA.z] = fmaf(bA.z, xs, v2);
        ap[wA.w] = fmaf(bA.w, xs, v3);
        ap[wB.x] = fmaf(bB.x, xs, v4);
        ap[wB.y] = fmaf(bB.y, xs, v5);
        ap[wB.z] = fmaf(bB.z, xs, v6);
        ap[wB.w] = fmaf(bB.w, xs, v7);
    }
    float di = g_deginv[v];
    __half* o = &g_FvH[(uint64_t)node * KK + c];
    #pragma unroll
    for (int k = 0; k < TOTK; k++) o[k * HH] = __float2half(ap[k * HH] * di);
    o[TOTK * HH] = __float2half(feat[node * stride + c]);
}

// ---------------- FP16 mma.sync m16n8k16 GEMM, NG output groups per A pass ----------------
// Block 64(M) x 64(N)/group; 128 thr (4 warps 2x2, warp tile 32x32). fp32 accumulate.
// Smem rows pitch 40 halfs -> all fragment LDS.32 conflict-free.
template <int NG, int EPI>
__global__ void __launch_bounds__(128) k_gemm(const __half* __restrict__ Bw,
                                              const float* __restrict__ bias,
                                              const float* __restrict__ extra,
                                              float* __restrict__ out) {
    extern __shared__ __half smem[];
    __half* As = smem;                       // [2][64][40]
    __half* Bs = smem + 2 * 64 * 40;         // [2][NG*64][40]
    const int ABUF = 64 * 40;                // halfs per A stage
    const int BBUF = NG * 64 * 40;           // halfs per B stage

    const int tid  = threadIdx.x;
    const int m0   = blockIdx.x * 64;
    const int lane = tid & 31, wid = tid >> 5;
    const int wm = (wid & 1) * 32, wn = (wid >> 1) * 32;
    const int g  = lane >> 2,  tq = lane & 3;

    float c[NG][2][4][4];
    #pragma unroll
    for (int gg = 0; gg < NG; gg++)
        #pragma unroll
        for (int mt = 0; mt < 2; mt++)
            #pragma unroll
            for (int nt = 0; nt < 4; nt++)
                #pragma unroll
                for (int i = 0; i < 4; i++) c[gg][mt][nt][i] = 0.0f;

    const uint32_t sA = smem_u32(As);
    const uint32_t sB = smem_u32(Bs);

    // one K-chunk = 32 halfs = 64B per row; 16B segments: 4/row
    auto load_tiles = [&](int kc, int st) {
        #pragma unroll
        for (int i = 0; i < 2; i++) {
            int seg = tid + i * 128;
            int row = seg >> 2, so = seg & 3;
            uint32_t dst = sA + (uint32_t)(st * ABUF + row * 40 + so * 8) * 2;
            cp16(dst, &g_FvH[(uint64_t)(m0 + row) * KK + kc * 32 + so * 8]);
        }
        #pragma unroll
        for (int i = 0; i < NG * 2; i++) {
            int seg = tid + i * 128;
            int row = seg >> 2, so = seg & 3;
            uint32_t dst = sB + (uint32_t)(st * BBUF + row * 40 + so * 8) * 2;
            cp16(dst, &Bw[(uint64_t)row * KK + kc * 32 + so * 8]);
        }
    };

    const int NCH = KK / 32;   // 56
    load_tiles(0, 0);
    CP_COMMIT();

    for (int ck = 0; ck < NCH; ck++) {
        CP_WAIT0();
        __syncthreads();
        if (ck + 1 < NCH) { load_tiles(ck + 1, (ck + 1) & 1); CP_COMMIT(); }
        const int buf = ck & 1;
        #pragma unroll
        for (int kh = 0; kh < 2; kh++) {          // two k16 halves of the 32-chunk
            const int kb = kh * 16;
            uint32_t a[2][4];
            #pragma unroll
            for (int mt = 0; mt < 2; mt++) {
                int r0 = buf * ABUF + (wm + mt * 16 + g) * 40 + kb + 2 * tq;
                int r1 = r0 + 8 * 40;
                a[mt][0] = *(const uint32_t*)&As[r0];
                a[mt][1] = *(const uint32_t*)&As[r1];
                a[mt][2] = *(const uint32_t*)&As[r0 + 8];
                a[mt][3] = *(const uint32_t*)&As[r1 + 8];
            }
            #pragma unroll
            for (int gg = 0; gg < NG; gg++) {
                uint32_t b[4][2];
                #pragma unroll
                for (int nt = 0; nt < 4; nt++) {
                    int br = buf * BBUF + (gg * 64 + wn + nt * 8 + g) * 40 + kb + 2 * tq;
                    b[nt][0] = *(const uint32_t*)&Bs[br];
                    b[nt][1] = *(const uint32_t*)&Bs[br + 8];
                }
                #pragma unroll
                for (int mt = 0; mt < 2; mt++)
                    #pragma unroll
                    for (int nt = 0; nt < 4; nt++) {
                        float* cc = c[gg][mt][nt];
                        asm volatile(
                            "mma.sync.aligned.m16n8k16.row.col.f32.f16.f16.f32 "
                            "{%0,%1,%2,%3},{%4,%5,%6,%7},{%8,%9},{%0,%1,%2,%3};"
                            : "+f"(cc[0]), "+f"(cc[1]), "+f"(cc[2]), "+f"(cc[3])
                            : "r"(a[mt][0]), "r"(a[mt][1]), "r"(a[mt][2]), "r"(a[mt][3]),
                              "r"(b[nt][0]), "r"(b[nt][1]));
                    }
            }
        }
        __syncthreads();
    }

    // epilogue
    #pragma unroll
    for (int gg = 0; gg < NG; gg++) {
        float* outg = out + gg * VH;
        const float* biasg = bias + gg * 64;
        #pragma unroll
        for (int mt = 0; mt < 2; mt++) {
            #pragma unroll
            for (int nt = 0; nt < 4; nt++) {
                int col = wn + nt * 8 + 2 * tq;
                float b0 = biasg[col], b1 = biasg[col + 1];
                #pragma unroll
                for (int half = 0; half < 2; half++) {
                    int row = m0 + wm + mt * 16 + g + half * 8;
                    float v0 = c[gg][mt][nt][half * 2 + 0] + b0;
                    float v1 = c[gg][mt][nt][half * 2 + 1] + b1;
                    if (EPI == 1) {
                        v0 = (v0 > 0.0f) ? v0 : (expf(v0) - 1.0f);
                        v1 = (v1 > 0.0f) ? v1 : (expf(v1) - 1.0f);
                    }
                    int o = row * 64 + col;
                    if (EPI == 2) {
                        float2 e2 = *(const float2*)&extra[o];
                        v0 = e2.x + tanhf(v0);
                        v1 = e2.y + tanhf(v1);
                    }
                    *(float2*)&outg[o] = make_float2(v0, v1);
                }
            }
        }
    }
}

// ---------------- GRU gates + output ----------------
__global__ void k_gates(float* __restrict__ out, int t) {
    int i = blockIdx.x * blockDim.x + threadIdx.x;
    float rx = g_xg[i], zx = g_xg[VH + i], nx = g_xg[2 * VH + i];
    float hr = g_hz[i], zh = g_hz[VH + i], ho = g_ho[i];
    float r = 1.0f / (1.0f + expf(-(rx + hr)));
    float z = 1.0f / (1.0f + expf(-(zx + zh)));
    float n = tanhf(nx + r * hr);
    float h = (1.0f - z) * n + z * ho;
    g_h[i] = h;
    int node = i >> 6, c = i & 63;
    out[(node * TT + t) * HH + c] = h;
}

// ---------------- launch ----------------
extern "C" void kernel_launch(void* const* d_in, const int* in_sizes, int n_in,
                              void* d_out, int out_size) {
    const float* x     = (const float*)d_in[0];
    const float* attr  = (const float*)d_in[1];
    const float* Wk    = (const float*)d_in[2];
    const float* Wroot = (const float*)d_in[3];
    const float* bias  = (const float*)d_in[4];
    const int*   eidx  = (const int*)d_in[5];
    float*       out   = (float*)d_out;

    __half* pWt;  float *pBias, *pH, *pA, *pHO, *pHZ, *pXG;
    cudaGetSymbolAddress((void**)&pWt,   g_WtH);
    cudaGetSymbolAddress((void**)&pBias, g_biasP);
    cudaGetSymbolAddress((void**)&pH,    g_h);
    cudaGetSymbolAddress((void**)&pA,    g_a);
    cudaGetSymbolAddress((void**)&pHO,   g_ho);
    cudaGetSymbolAddress((void**)&pHZ,   g_hz);
    cudaGetSymbolAddress((void**)&pXG,   g_xg);

    const int SM1 = (2 * 64 * 40 + 2 * 1 * 64 * 40) * 2;   // 20480
    const int SM2 = (2 * 64 * 40 + 2 * 2 * 64 * 40) * 2;   // 30720
    const int SM3 = (2 * 64 * 40 + 2 * 3 * 64 * 40) * 2;   // 40960
    cudaFuncSetAttribute(k_gemm<1, 1>, cudaFuncAttributeMaxDynamicSharedMemorySize, SM1);
    cudaFuncSetAttribute(k_gemm<1, 2>, cudaFuncAttributeMaxDynamicSharedMemorySize, SM1);
    cudaFuncSetAttribute(k_gemm<2, 0>, cudaFuncAttributeMaxDynamicSharedMemorySize, SM2);
    cudaFuncSetAttribute(k_gemm<3, 0>, cudaFuncAttributeMaxDynamicSharedMemorySize, SM3);

    k_prep<<<(NCONV * HH * KK + 255) / 256, 256>>>(Wk, Wroot, bias, attr);
    k_scan<<<1, 1024>>>(eidx);
    k_fill<<<VV / 8, 256>>>(eidx);

    const dim3 sblk(64, 4);
    const int  HK = HH * KK;
    const int  GG = VT / 64;     // 128

    for (int t = 0; t < TT; t++) {
        // ODE: a = elu(conv5(h)) ; ho = h + tanh(conv6(a))
        k_scatter<<<VT / 4, sblk>>>(pH, HH);
        k_gemm<1, 1><<<GG, 128, SM1>>>(pWt + 5 * HK, pBias + 5 * HH, nullptr, pA);
        k_scatter<<<VT / 4, sblk>>>(pA, HH);
        k_gemm<1, 2><<<GG, 128, SM1>>>(pWt + 6 * HK, pBias + 6 * HH, pH, pHO);
        // GRU h-side fused: [hr | zh] = conv{1,3}(ho)
        k_scatter<<<VT / 4, sblk>>>(pHO, HH);
        k_gemm<2, 0><<<GG, 128, SM2>>>(pWt + 3 * HK, pBias + 3 * HH, nullptr, pHZ);
        // GRU x-side fused: [rx | zx | nx] = conv{0,2,4}(x_t)
        k_scatter<<<VT / 4, sblk>>>(x + t * HH, TT * HH);
        k_gemm<3, 0><<<GG, 128, SM3>>>(pWt, pBias, nullptr, pXG);
        // gates + output
        k_gates<<<VH / 256, 256>>>(out, t);
    }
}

// round 8
// speedup vs baseline: 2.4045x; 1.4240x over previous
#include <cuda_runtime.h>
#include <cuda_fp16.h>
#include <cstdint>
#include <math.h>

#define BB 4
#define VV 2048
#define TT 12
#define HH 64
#define EE 32768
#define VT (BB*VV)            /* 8192 */
#define TOTK 27
#define KK (TOTK*HH + HH)     /* 1792 */
#define NCONV 7
#define VH (VT*HH)

// ================= helpers =================
__device__ __forceinline__ uint32_t smem_u32(const void* p) {
    uint32_t a;
    asm("{ .reg .u64 t; cvta.to.shared.u64 t, %1; cvt.u32.u64 %0, t; }" : "=r"(a) : "l"(p));
    return a;
}
__device__ __forceinline__ void cp16(uint32_t dst, const void* src) {
    asm volatile("cp.async.ca.shared.global [%0], [%1], 16;" :: "r"(dst), "l"(src));
}
#define CP_COMMIT() asm volatile("cp.async.commit_group;" ::: "memory")
#define CP_WAIT0()  asm volatile("cp.async.wait_group 0;" ::: "memory")

// ================= persistent device scratch =================
__device__ __align__(256) __half          g_FvH[VT * KK];             // 29.4 MB (h-side)
__device__ __align__(256) __half          g_FvX[(size_t)TT * VT * KK]; // 352 MB (x-side, all t)
__device__ __align__(256) __half          g_WtH[NCONV * HH * KK];     // [perm conv][n][k]
__device__ __align__(256) float           g_biasP[NCONV * HH];
__device__ __align__(256) float           g_basis[EE * 8];
__device__ __align__(256) int             g_cell[EE];                  // lo0 + 2*lo1 + 4*lo2
// CSR-ordered edge tables (chain-free scatter)
__device__ __align__(256) float           g_basisC[EE * 8];
__device__ __align__(256) int             g_scC[EE];                   // src | (cell<<16)
__device__ float          g_deginv[VV];
__device__ int            g_csroff[VV + 1];
__device__ __align__(256) float g_h [VH];
__device__ __align__(256) float g_a [VH];
__device__ __align__(256) float g_ho[VH];
__device__ __align__(256) float g_hz[2 * VH];             // hr, zh
__device__ __align__(256) float g_xg[(size_t)TT * 3 * VH]; // [t][rx,zx,nx]

// ---------------- prep: weight pack (fp16) + spline basis/cell + zero h ----------------
__global__ void k_prep(const float* __restrict__ Wk, const float* __restrict__ Wroot,
                       const float* __restrict__ bias, const float* __restrict__ attr) {
    int idx = blockIdx.x * blockDim.x + threadIdx.x;
    if (idx < VH) g_h[idx] = 0.0f;
    if (idx < EE) {
        int e = idx;
        float fr[3]; int lo[3];
        #pragma unroll
        for (int d = 0; d < 3; d++) {
            float u  = attr[e * 3 + d] * 2.0f;
            float fl = fminf(fmaxf(floorf(u), 0.0f), 1.0f);
            fr[d] = u - fl;
            lo[d] = (int)fl;
        }
        #pragma unroll
        for (int s = 0; s < 8; s++) {
            int b0 = s & 1, b1 = (s >> 1) & 1, b2 = (s >> 2) & 1;
            float b = (b0 ? fr[0] : 1.0f - fr[0])
                    * (b1 ? fr[1] : 1.0f - fr[1])
                    * (b2 ? fr[2] : 1.0f - fr[2]);
            g_basis[e * 8 + s] = b;
        }
        g_cell[e] = lo[0] + 2 * lo[1] + 4 * lo[2];
    }
    if (idx >= NCONV * HH * KK) return;
    int k = idx % KK;
    int n = (idx / KK) & 63;
    int p = idx / (KK * HH);
    const int perm[7] = {0, 2, 4, 1, 3, 5, 6};
    int conv = perm[p];
    float v = (k < TOTK * HH) ? Wk[(conv * TOTK * HH + k) * HH + n]
                              : Wroot[(conv * HH + (k - TOTK * HH)) * HH + n];
    g_WtH[idx] = __float2half(v);
    if (k == 0) g_biasP[p * HH + n] = bias[conv * HH + n];
}

// ---------------- degree histogram + exclusive scan (single block) ----------------
__global__ void k_scan(const int* __restrict__ eidx) {
    __shared__ int sdeg[VV];
    __shared__ int soff[VV + 1];
    int tid = threadIdx.x;
    for (int v = tid; v < VV; v += blockDim.x) sdeg[v] = 0;
    __syncthreads();
    const int* dst = eidx + EE;
    for (int e = tid; e < EE; e += blockDim.x) atomicAdd(&sdeg[dst[e]], 1);
    __syncthreads();
    if (tid == 0) {
        int a = 0;
        for (int v = 0; v < VV; v++) { soff[v] = a; a += sdeg[v]; }
        soff[VV] = a;
    }
    __syncthreads();
    for (int v = tid; v < VV; v += blockDim.x) {
        g_csroff[v] = soff[v];
        g_deginv[v] = 1.0f / (float)max(sdeg[v], 1);
    }
    if (tid == 0) g_csroff[VV] = soff[VV];
}

// ---------------- CSR fill (ballot-ordered, deterministic) ----------------
__global__ void k_fill(const int* __restrict__ eidx) {
    int warp = (blockIdx.x * blockDim.x + threadIdx.x) >> 5;
    int lane = threadIdx.x & 31;
    if (warp >= VV) return;
    const int* dst = eidx + EE;
    int cnt = g_csroff[warp];
    for (int base = 0; base < EE; base += 32) {
        int d = dst[base + lane];
        unsigned m = __ballot_sync(0xFFFFFFFFu, d == warp);
        if (d == warp) {
            int pos = cnt + __popc(m & ((1u << lane) - 1u));
            int e = base + lane;
            g_scC[pos] = eidx[e] | (g_cell[e] << 16);
            *(float4*)&g_basisC[pos * 8]     = *(const float4*)&g_basis[e * 8];
            *(float4*)&g_basisC[pos * 8 + 4] = *(const float4*)&g_basis[e * 8 + 4];
        }
        cnt += __popc(m);
    }
}

// ---------------- scatter: register accumulators + uniform cell switch ----------------
// slots for cell (L0,L1,L2): k(s) = (L0+b0) + 3(L1+b1) + 9(L2+b2), static per case.
template <int L0, int L1, int L2>
__device__ __forceinline__ void upd(float* acc, const float* bas, float xs) {
    #pragma unroll
    for (int s = 0; s < 8; s++) {
        int k = (L0 + (s & 1)) + 3 * (L1 + ((s >> 1) & 1)) + 9 * (L2 + ((s >> 2) & 1));
        acc[k] = fmaf(bas[s], xs, acc[k]);
    }
}

__global__ void __launch_bounds__(256) k_scatter(const float* __restrict__ feat, int stride,
                                                 __half* __restrict__ dst) {
    int c    = threadIdx.x;            // 0..63 channel
    int nsub = threadIdx.y;            // 0..3
    int node = blockIdx.x * 4 + nsub;
    int b = node >> 11;
    int v = node & (VV - 1);
    feat += (size_t)blockIdx.y * HH;                 // x-batch: t offset into x
    dst  += (size_t)blockIdx.y * VT * KK;            // x-batch: t slab of FvX

    float acc[TOTK];
    #pragma unroll
    for (int k = 0; k < TOTK; k++) acc[k] = 0.0f;

    int i0 = g_csroff[v], i1 = g_csroff[v + 1];
    int base = b * VV;
    for (int ii = i0; ii < i1; ii++) {
        float4 bA = *(const float4*)&g_basisC[ii * 8];
        float4 bB = *(const float4*)&g_basisC[ii * 8 + 4];
        int    sc = g_scC[ii];
        float  xs = feat[(size_t)(base + (sc & 0xFFFF)) * stride + c];
        float bas[8] = {bA.x, bA.y, bA.z, bA.w, bB.x, bB.y, bB.z, bB.w};
        switch (sc >> 16) {                          // warp-uniform: no divergence
            case 0: upd<0,0,0>(acc, bas, xs); break;
            case 1: upd<1,0,0>(acc, bas, xs); break;
            case 2: upd<0,1,0>(acc, bas, xs); break;
            case 3: upd<1,1,0>(acc, bas, xs); break;
            case 4: upd<0,0,1>(acc, bas, xs); break;
            case 5: upd<1,0,1>(acc, bas, xs); break;
            case 6: upd<0,1,1>(acc, bas, xs); break;
            case 7: upd<1,1,1>(acc, bas, xs); break;
        }
    }
    float di = g_deginv[v];
    __half* o = dst + (size_t)node * KK + c;
    #pragma unroll
    for (int k = 0; k < TOTK; k++) o[k * HH] = __float2half(acc[k] * di);
    o[TOTK * HH] = __float2half(feat[(size_t)node * stride + c]);
}

// ---------------- FP16 mma.sync m16n8k16 GEMM, NG output groups per A pass ----------------
// Block 64(M) x 64(N)/group; 128 thr (4 warps 2x2, warp tile 32x32). fp32 accumulate.
// BATCH=1: A has TT*VT rows; output row (t*8192+node) -> out[(t*NG+gg)*VH + node*64+col].
template <int NG, int EPI, int BATCH>
__global__ void __launch_bounds__(128) k_gemm(const __half* __restrict__ Ab,
                                              const __half* __restrict__ Bw,
                                              const float* __restrict__ bias,
                                              const float* __restrict__ extra,
                                              float* __restrict__ out) {
    extern __shared__ __half smem[];
    __half* As = smem;                       // [2][64][40]
    __half* Bs = smem + 2 * 64 * 40;         // [2][NG*64][40]
    const int ABUF = 64 * 40;
    const int BBUF = NG * 64 * 40;

    const int tid  = threadIdx.x;
    const int m0   = blockIdx.x * 64;
    const int lane = tid & 31, wid = tid >> 5;
    const int wm = (wid & 1) * 32, wn = (wid >> 1) * 32;
    const int g  = lane >> 2,  tq = lane & 3;

    float c[NG][2][4][4];
    #pragma unroll
    for (int gg = 0; gg < NG; gg++)
        #pragma unroll
        for (int mt = 0; mt < 2; mt++)
            #pragma unroll
            for (int nt = 0; nt < 4; nt++)
                #pragma unroll
                for (int i = 0; i < 4; i++) c[gg][mt][nt][i] = 0.0f;

    const uint32_t sA = smem_u32(As);
    const uint32_t sB = smem_u32(Bs);

    auto load_tiles = [&](int kc, int st) {
        #pragma unroll
        for (int i = 0; i < 2; i++) {
            int seg = tid + i * 128;
            int row = seg >> 2, so = seg & 3;
            uint32_t dst = sA + (uint32_t)(st * ABUF + row * 40 + so * 8) * 2;
            cp16(dst, &Ab[(size_t)(m0 + row) * KK + kc * 32 + so * 8]);
        }
        #pragma unroll
        for (int i = 0; i < NG * 2; i++) {
            int seg = tid + i * 128;
            int row = seg >> 2, so = seg & 3;
            uint32_t dst = sB + (uint32_t)(st * BBUF + row * 40 + so * 8) * 2;
            cp16(dst, &Bw[(size_t)row * KK + kc * 32 + so * 8]);
        }
    };

    const int NCH = KK / 32;   // 56
    load_tiles(0, 0);
    CP_COMMIT();

    for (int ck = 0; ck < NCH; ck++) {
        CP_WAIT0();
        __syncthreads();
        if (ck + 1 < NCH) { load_tiles(ck + 1, (ck + 1) & 1); CP_COMMIT(); }
        const int buf = ck & 1;
        #pragma unroll
        for (int kh = 0; kh < 2; kh++) {
            const int kb = kh * 16;
            uint32_t a[2][4];
            #pragma unroll
            for (int mt = 0; mt < 2; mt++) {
                int r0 = buf * ABUF + (wm + mt * 16 + g) * 40 + kb + 2 * tq;
                int r1 = r0 + 8 * 40;
                a[mt][0] = *(const uint32_t*)&As[r0];
                a[mt][1] = *(const uint32_t*)&As[r1];
                a[mt][2] = *(const uint32_t*)&As[r0 + 8];
                a[mt][3] = *(const uint32_t*)&As[r1 + 8];
            }
            #pragma unroll
            for (int gg = 0; gg < NG; gg++) {
                uint32_t b[4][2];
                #pragma unroll
                for (int nt = 0; nt < 4; nt++) {
                    int br = buf * BBUF + (gg * 64 + wn + nt * 8 + g) * 40 + kb + 2 * tq;
                    b[nt][0] = *(const uint32_t*)&Bs[br];
                    b[nt][1] = *(const uint32_t*)&Bs[br + 8];
                }
                #pragma unroll
                for (int mt = 0; mt < 2; mt++)
                    #pragma unroll
                    for (int nt = 0; nt < 4; nt++) {
                        float* cc = c[gg][mt][nt];
                        asm volatile(
                            "mma.sync.aligned.m16n8k16.row.col.f32.f16.f16.f32 "
                            "{%0,%1,%2,%3},{%4,%5,%6,%7},{%8,%9},{%0,%1,%2,%3};"
                            : "+f"(cc[0]), "+f"(cc[1]), "+f"(cc[2]), "+f"(cc[3])
                            : "r"(a[mt][0]), "r"(a[mt][1]), "r"(a[mt][2]), "r"(a[mt][3]),
                              "r"(b[nt][0]), "r"(b[nt][1]));
                    }
            }
        }
        __syncthreads();
    }

    // epilogue
    #pragma unroll
    for (int gg = 0; gg < NG; gg++) {
        const float* biasg = bias + gg * 64;
        #pragma unroll
        for (int mt = 0; mt < 2; mt++) {
            #pragma unroll
            for (int nt = 0; nt < 4; nt++) {
                int col = wn + nt * 8 + 2 * tq;
                float b0 = biasg[col], b1 = biasg[col + 1];
                #pragma unroll
                for (int half = 0; half < 2; half++) {
                    int row = m0 + wm + mt * 16 + g + half * 8;
                    float v0 = c[gg][mt][nt][half * 2 + 0] + b0;
                    float v1 = c[gg][mt][nt][half * 2 + 1] + b1;
                    if (EPI == 1) {
                        v0 = (v0 > 0.0f) ? v0 : (expf(v0) - 1.0f);
                        v1 = (v1 > 0.0f) ? v1 : (expf(v1) - 1.0f);
                    }
                    size_t o;
                    if (BATCH) {
                        int tb = row >> 13, nd = row & (VT - 1);
                        o = ((size_t)(tb * NG + gg) * VT + nd) * 64 + col;
                    } else {
                        o = (size_t)gg * VH + (size_t)row * 64 + col;
                    }
                    if (EPI == 2) {
                        float2 e2 = *(const float2*)&extra[(size_t)row * 64 + col];
                        v0 = e2.x + tanhf(v0);
                        v1 = e2.y + tanhf(v1);
                    }
                    *(float2*)&out[o] = make_float2(v0, v1);
                }
            }
        }
    }
}

// ---------------- GRU gates + output ----------------
__global__ void k_gates(float* __restrict__ out, const float* __restrict__ xgt, int t) {
    int i = blockIdx.x * blockDim.x + threadIdx.x;
    float rx = xgt[i], zx = xgt[VH + i], nx = xgt[2 * VH + i];
    float hr = g_hz[i], zh = g_hz[VH + i], ho = g_ho[i];
    float r = 1.0f / (1.0f + expf(-(rx + hr)));
    float z = 1.0f / (1.0f + expf(-(zx + zh)));
    float n = tanhf(nx + r * hr);
    float h = (1.0f - z) * n + z * ho;
    g_h[i] = h;
    int node = i >> 6, c = i & 63;
    out[((size_t)node * TT + t) * HH + c] = h;
}

// ---------------- launch ----------------
extern "C" void kernel_launch(void* const* d_in, const int* in_sizes, int n_in,
                              void* d_out, int out_size) {
    const float* x     = (const float*)d_in[0];
    const float* attr  = (const float*)d_in[1];
    const float* Wk    = (const float*)d_in[2];
    const float* Wroot = (const float*)d_in[3];
    const float* bias  = (const float*)d_in[4];
    const int*   eidx  = (const int*)d_in[5];
    float*       out   = (float*)d_out;

    __half *pWt, *pFvH, *pFvX;
    float *pBias, *pH, *pA, *pHO, *pHZ, *pXG;
    cudaGetSymbolAddress((void**)&pWt,   g_WtH);
    cudaGetSymbolAddress((void**)&pFvH,  g_FvH);
    cudaGetSymbolAddress((void**)&pFvX,  g_FvX);
    cudaGetSymbolAddress((void**)&pBias, g_biasP);
    cudaGetSymbolAddress((void**)&pH,    g_h);
    cudaGetSymbolAddress((void**)&pA,    g_a);
    cudaGetSymbolAddress((void**)&pHO,   g_ho);
    cudaGetSymbolAddress((void**)&pHZ,   g_hz);
    cudaGetSymbolAddress((void**)&pXG,   g_xg);

    const int SM1 = (2 * 64 * 40 + 2 * 1 * 64 * 40) * 2;   // 20480
    const int SM2 = (2 * 64 * 40 + 2 * 2 * 64 * 40) * 2;   // 30720
    const int SM3 = (2 * 64 * 40 + 2 * 3 * 64 * 40) * 2;   // 40960
    cudaFuncSetAttribute(k_gemm<1, 1, 0>, cudaFuncAttributeMaxDynamicSharedMemorySize, SM1);
    cudaFuncSetAttribute(k_gemm<1, 2, 0>, cudaFuncAttributeMaxDynamicSharedMemorySize, SM1);
    cudaFuncSetAttribute(k_gemm<2, 0, 0>, cudaFuncAttributeMaxDynamicSharedMemorySize, SM2);
    cudaFuncSetAttribute(k_gemm<3, 0, 1>, cudaFuncAttributeMaxDynamicSharedMemorySize, SM3);

    k_prep<<<(NCONV * HH * KK + 255) / 256, 256>>>(Wk, Wroot, bias, attr);
    k_scan<<<1, 1024>>>(eidx);
    k_fill<<<VV / 8, 256>>>(eidx);

    const dim3 sblk(64, 4);
    const int  HK = HH * KK;
    const int  GG = VT / 64;     // 128

    // ---- x-side hoisted: scatter all 12 t, then one batched NG=3 GEMM ----
    k_scatter<<<dim3(VT / 4, TT), sblk>>>(x, TT * HH, pFvX);
    k_gemm<3, 0, 1><<<GG * TT, 128, SM3>>>(pFvX, pWt, pBias, nullptr, pXG);

    for (int t = 0; t < TT; t++) {
        // ODE: a = elu(conv5(h)) ; ho = h + tanh(conv6(a))
        k_scatter<<<VT / 4, sblk>>>(pH, HH, pFvH);
        k_gemm<1, 1, 0><<<GG, 128, SM1>>>(pFvH, pWt + 5 * HK, pBias + 5 * HH, nullptr, pA);
        k_scatter<<<VT / 4, sblk>>>(pA, HH, pFvH);
        k_gemm<1, 2, 0><<<GG, 128, SM1>>>(pFvH, pWt + 6 * HK, pBias + 6 * HH, pH, pHO);
        // GRU h-side fused: [hr | zh] = conv{1,3}(ho)
        k_scatter<<<VT / 4, sblk>>>(pHO, HH, pFvH);
        k_gemm<2, 0, 0><<<GG, 128, SM2>>>(pFvH, pWt + 3 * HK, pBias + 3 * HH, nullptr, pHZ);
        // gates + output
        k_gates<<<VH / 256, 256>>>(out, pXG + (size_t)t * 3 * VH, t);
    }
}

// round 9
// speedup vs baseline: 2.6738x; 1.1120x over previous
#include <cuda_runtime.h>
#include <cuda_fp16.h>
#include <cstdint>
#include <math.h>

#define BB 4
#define VV 2048
#define TT 12
#define HH 64
#define EE 32768
#define VT (BB*VV)            /* 8192 */
#define TOTK 27
#define KK (TOTK*HH + HH)     /* 1792 */
#define NCONV 7
#define VH (VT*HH)

// ================= helpers =================
__device__ __forceinline__ uint32_t smem_u32(const void* p) {
    uint32_t a;
    asm("{ .reg .u64 t; cvta.to.shared.u64 t, %1; cvt.u32.u64 %0, t; }" : "=r"(a) : "l"(p));
    return a;
}
__device__ __forceinline__ void cp16(uint32_t dst, const void* src) {
    asm volatile("cp.async.ca.shared.global [%0], [%1], 16;" :: "r"(dst), "l"(src));
}
#define CP_COMMIT() asm volatile("cp.async.commit_group;" ::: "memory")
#define CP_WAIT0()  asm volatile("cp.async.wait_group 0;" ::: "memory")
#define BARH(id)    asm volatile("bar.sync %0, 128;" :: "r"((id) + 1) : "memory")

// ================= persistent device scratch =================
__device__ __align__(256) __half          g_FvH[VT * KK];              // 29.4 MB (h-side)
__device__ __align__(256) __half          g_FvX[(size_t)TT * VT * KK]; // 352 MB (x-side, all t)
__device__ __align__(256) __half          g_WtH[NCONV * HH * KK];      // [perm conv][n][k]
__device__ __align__(256) float           g_biasP[NCONV * HH];
__device__ __align__(256) float           g_basis[EE * 8];
__device__ __align__(256) int             g_cell[EE];                  // lo0 + 2*lo1 + 4*lo2
// CSR-ordered edge tables (chain-free scatter)
__device__ __align__(256) float           g_basisC[EE * 8];
__device__ __align__(256) int             g_scC[EE];                   // src | (cell<<16)
__device__ float          g_deginv[VV];
__device__ int            g_csroff[VV + 1];
__device__ __align__(256) float g_h [VH];
__device__ __align__(256) float g_a [VH];
__device__ __align__(256) float g_ho[VH];
__device__ __align__(256) float g_hz[2 * VH];              // hr, zh
__device__ __align__(256) float g_xg[(size_t)TT * 3 * VH]; // [t][rx,zx,nx]

// ---------------- prep: weight pack (fp16) + spline basis/cell + zero h ----------------
__global__ void k_prep(const float* __restrict__ Wk, const float* __restrict__ Wroot,
                       const float* __restrict__ bias, const float* __restrict__ attr) {
    int idx = blockIdx.x * blockDim.x + threadIdx.x;
    if (idx < VH) g_h[idx] = 0.0f;
    if (idx < EE) {
        int e = idx;
        float fr[3]; int lo[3];
        #pragma unroll
        for (int d = 0; d < 3; d++) {
            float u  = attr[e * 3 + d] * 2.0f;
            float fl = fminf(fmaxf(floorf(u), 0.0f), 1.0f);
            fr[d] = u - fl;
            lo[d] = (int)fl;
        }
        #pragma unroll
        for (int s = 0; s < 8; s++) {
            int b0 = s & 1, b1 = (s >> 1) & 1, b2 = (s >> 2) & 1;
            float b = (b0 ? fr[0] : 1.0f - fr[0])
                    * (b1 ? fr[1] : 1.0f - fr[1])
                    * (b2 ? fr[2] : 1.0f - fr[2]);
            g_basis[e * 8 + s] = b;
        }
        g_cell[e] = lo[0] + 2 * lo[1] + 4 * lo[2];
    }
    if (idx >= NCONV * HH * KK) return;
    int k = idx % KK;
    int n = (idx / KK) & 63;
    int p = idx / (KK * HH);
    const int perm[7] = {0, 2, 4, 1, 3, 5, 6};
    int conv = perm[p];
    float v = (k < TOTK * HH) ? Wk[(conv * TOTK * HH + k) * HH + n]
                              : Wroot[(conv * HH + (k - TOTK * HH)) * HH + n];
    g_WtH[idx] = __float2half(v);
    if (k == 0) g_biasP[p * HH + n] = bias[conv * HH + n];
}

// ---------------- degree histogram + exclusive scan (single block) ----------------
__global__ void k_scan(const int* __restrict__ eidx) {
    __shared__ int sdeg[VV];
    __shared__ int soff[VV + 1];
    int tid = threadIdx.x;
    for (int v = tid; v < VV; v += blockDim.x) sdeg[v] = 0;
    __syncthreads();
    const int* dst = eidx + EE;
    for (int e = tid; e < EE; e += blockDim.x) atomicAdd(&sdeg[dst[e]], 1);
    __syncthreads();
    if (tid == 0) {
        int a = 0;
        for (int v = 0; v < VV; v++) { soff[v] = a; a += sdeg[v]; }
        soff[VV] = a;
    }
    __syncthreads();
    for (int v = tid; v < VV; v += blockDim.x) {
        g_csroff[v] = soff[v];
        g_deginv[v] = 1.0f / (float)max(sdeg[v], 1);
    }
    if (tid == 0) g_csroff[VV] = soff[VV];
}

// ---------------- CSR fill (ballot-ordered, deterministic) ----------------
__global__ void k_fill(const int* __restrict__ eidx) {
    int warp = (blockIdx.x * blockDim.x + threadIdx.x) >> 5;
    int lane = threadIdx.x & 31;
    if (warp >= VV) return;
    const int* dst = eidx + EE;
    int cnt = g_csroff[warp];
    for (int base = 0; base < EE; base += 32) {
        int d = dst[base + lane];
        unsigned m = __ballot_sync(0xFFFFFFFFu, d == warp);
        if (d == warp) {
            int pos = cnt + __popc(m & ((1u << lane) - 1u));
            int e = base + lane;
            g_scC[pos] = eidx[e] | (g_cell[e] << 16);
            *(float4*)&g_basisC[pos * 8]     = *(const float4*)&g_basis[e * 8];
            *(float4*)&g_basisC[pos * 8 + 4] = *(const float4*)&g_basis[e * 8 + 4];
        }
        cnt += __popc(m);
    }
}

// ---------------- scatter: register accumulators + uniform cell switch ----------------
template <int L0, int L1, int L2>
__device__ __forceinline__ void upd(float* acc, const float* bas, float xs) {
    #pragma unroll
    for (int s = 0; s < 8; s++) {
        int k = (L0 + (s & 1)) + 3 * (L1 + ((s >> 1) & 1)) + 9 * (L2 + ((s >> 2) & 1));
        acc[k] = fmaf(bas[s], xs, acc[k]);
    }
}

__global__ void __launch_bounds__(256) k_scatter(const float* __restrict__ feat, int stride,
                                                 __half* __restrict__ dst) {
    int c    = threadIdx.x;            // 0..63 channel
    int nsub = threadIdx.y;            // 0..3
    int node = blockIdx.x * 4 + nsub;
    int b = node >> 11;
    int v = node & (VV - 1);
    feat += (size_t)blockIdx.y * HH;                 // x-batch: t offset into x
    dst  += (size_t)blockIdx.y * VT * KK;            // x-batch: t slab of FvX

    float acc[TOTK];
    #pragma unroll
    for (int k = 0; k < TOTK; k++) acc[k] = 0.0f;

    int i0 = g_csroff[v], i1 = g_csroff[v + 1];
    int base = b * VV;
    for (int ii = i0; ii < i1; ii++) {
        float4 bA = *(const float4*)&g_basisC[ii * 8];
        float4 bB = *(const float4*)&g_basisC[ii * 8 + 4];
        int    sc = g_scC[ii];
        float  xs = feat[(size_t)(base + (sc & 0xFFFF)) * stride + c];
        float bas[8] = {bA.x, bA.y, bA.z, bA.w, bB.x, bB.y, bB.z, bB.w};
        switch (sc >> 16) {                          // warp-uniform: no divergence
            case 0: upd<0,0,0>(acc, bas, xs); break;
            case 1: upd<1,0,0>(acc, bas, xs); break;
            case 2: upd<0,1,0>(acc, bas, xs); break;
            case 3: upd<1,1,0>(acc, bas, xs); break;
            case 4: upd<0,0,1>(acc, bas, xs); break;
            case 5: upd<1,0,1>(acc, bas, xs); break;
            case 6: upd<0,1,1>(acc, bas, xs); break;
            case 7: upd<1,1,1>(acc, bas, xs); break;
        }
    }
    float di = g_deginv[v];
    __half* o = dst + (size_t)node * KK + c;
    #pragma unroll
    for (int k = 0; k < TOTK; k++) o[k * HH] = __float2half(acc[k] * di);
    o[TOTK * HH] = __float2half(feat[(size_t)node * stride + c]);
}

// ---------------- FP16 mma.sync GEMM: 256 thr, intra-CTA split-K (2 halves x 4 warps) ----
// Half p handles K-chunks ck ≡ p (mod 2), own smem double-buffer, named barriers.
// Final fp32 reduction via padded smem stage; epilogue by half 0.
template <int NG, int EPI, int BATCH>
__global__ void __launch_bounds__(256) k_gemm(const __half* __restrict__ Ab,
                                              const __half* __restrict__ Bw,
                                              const float* __restrict__ bias,
                                              const float* __restrict__ extra,
                                              float* __restrict__ out) {
    extern __shared__ __half smem[];
    const int ABUF = 64 * 40;            // halfs per A stage
    const int BBUF = NG * 64 * 40;       // halfs per B stage

    const int tid  = threadIdx.x;
    const int half = tid >> 7;           // K-split half
    const int htid = tid & 127;
    const int m0   = blockIdx.x * 64;
    const int lane = tid & 31, wid = (tid >> 5) & 3;
    const int wm = (wid & 1) * 32, wn = (wid >> 1) * 32;
    const int g  = lane >> 2,  tq = lane & 3;

    __half* As = smem + half * (2 * ABUF);
    __half* Bs = smem + 4 * ABUF + half * (2 * BBUF);

    float c[NG][2][4][4];
    #pragma unroll
    for (int gg = 0; gg < NG; gg++)
        #pragma unroll
        for (int mt = 0; mt < 2; mt++)
            #pragma unroll
            for (int nt = 0; nt < 4; nt++)
                #pragma unroll
                for (int i = 0; i < 4; i++) c[gg][mt][nt][i] = 0.0f;

    const uint32_t sA = smem_u32(As);
    const uint32_t sB = smem_u32(Bs);

    auto load_tiles = [&](int kc, int st) {
        #pragma unroll
        for (int i = 0; i < 2; i++) {
            int seg = htid + i * 128;
            int row = seg >> 2, so = seg & 3;
            uint32_t dst = sA + (uint32_t)(st * ABUF + row * 40 + so * 8) * 2;
            cp16(dst, &Ab[(size_t)(m0 + row) * KK + kc * 32 + so * 8]);
        }
        #pragma unroll
        for (int i = 0; i < NG * 2; i++) {
            int seg = htid + i * 128;
            int row = seg >> 2, so = seg & 3;
            uint32_t dst = sB + (uint32_t)(st * BBUF + row * 40 + so * 8) * 2;
            cp16(dst, &Bw[(size_t)row * KK + kc * 32 + so * 8]);
        }
    };

    const int NIT = (KK / 32) / 2;   // 28 chunks per half
    load_tiles(half, 0);
    CP_COMMIT();

    for (int it = 0; it < NIT; it++) {
        const int ck = half + 2 * it;
        CP_WAIT0();
        BARH(half);
        if (it + 1 < NIT) { load_tiles(ck + 2, (it + 1) & 1); CP_COMMIT(); }
        const int buf = it & 1;
        #pragma unroll
        for (int kh = 0; kh < 2; kh++) {
            const int kb = kh * 16;
            uint32_t a[2][4];
            #pragma unroll
            for (int mt = 0; mt < 2; mt++) {
                int r0 = buf * ABUF + (wm + mt * 16 + g) * 40 + kb + 2 * tq;
                int r1 = r0 + 8 * 40;
                a[mt][0] = *(const uint32_t*)&As[r0];
                a[mt][1] = *(const uint32_t*)&As[r1];
                a[mt][2] = *(const uint32_t*)&As[r0 + 8];
                a[mt][3] = *(const uint32_t*)&As[r1 + 8];
            }
            #pragma unroll
            for (int gg = 0; gg < NG; gg++) {
                uint32_t b[4][2];
                #pragma unroll
                for (int nt = 0; nt < 4; nt++) {
                    int br = buf * BBUF + (gg * 64 + wn + nt * 8 + g) * 40 + kb + 2 * tq;
                    b[nt][0] = *(const uint32_t*)&Bs[br];
                    b[nt][1] = *(const uint32_t*)&Bs[br + 8];
                }
                #pragma unroll
                for (int mt = 0; mt < 2; mt++)
                    #pragma unroll
                    for (int nt = 0; nt < 4; nt++) {
                        float* cc = c[gg][mt][nt];
                        asm volatile(
                            "mma.sync.aligned.m16n8k16.row.col.f32.f16.f16.f32 "
                            "{%0,%1,%2,%3},{%4,%5,%6,%7},{%8,%9},{%0,%1,%2,%3};"
                            : "+f"(cc[0]), "+f"(cc[1]), "+f"(cc[2]), "+f"(cc[3])
                            : "r"(a[mt][0]), "r"(a[mt][1]), "r"(a[mt][2]), "r"(a[mt][3]),
                              "r"(b[nt][0]), "r"(b[nt][1]));
                    }
            }
        }
        BARH(half);
    }

    // ---- cross-half reduction (padded stage: stride 32*NG+1 -> conflict-free) ----
    __syncthreads();
    float* red = (float*)smem;
    const int RP = 32 * NG + 1;
    if (half == 1) {
        float* r = &red[htid * RP];
        int ix = 0;
        #pragma unroll
        for (int gg = 0; gg < NG; gg++)
            #pragma unroll
            for (int mt = 0; mt < 2; mt++)
                #pragma unroll
                for (int nt = 0; nt < 4; nt++)
                    #pragma unroll
                    for (int i = 0; i < 4; i++) r[ix++] = c[gg][mt][nt][i];
    }
    __syncthreads();
    if (half == 1) return;
    {
        const float* r = &red[htid * RP];
        int ix = 0;
        #pragma unroll
        for (int gg = 0; gg < NG; gg++)
            #pragma unroll
            for (int mt = 0; mt < 2; mt++)
                #pragma unroll
                for (int nt = 0; nt < 4; nt++)
                    #pragma unroll
                    for (int i = 0; i < 4; i++) c[gg][mt][nt][i] += r[ix++];
    }

    // ---- epilogue (half 0 only) ----
    #pragma unroll
    for (int gg = 0; gg < NG; gg++) {
        const float* biasg = bias + gg * 64;
        #pragma unroll
        for (int mt = 0; mt < 2; mt++) {
            #pragma unroll
            for (int nt = 0; nt < 4; nt++) {
                int col = wn + nt * 8 + 2 * tq;
                float b0 = biasg[col], b1 = biasg[col + 1];
                #pragma unroll
                for (int hf = 0; hf < 2; hf++) {
                    int row = m0 + wm + mt * 16 + g + hf * 8;
                    float v0 = c[gg][mt][nt][hf * 2 + 0] + b0;
                    float v1 = c[gg][mt][nt][hf * 2 + 1] + b1;
                    if (EPI == 1) {
                        v0 = (v0 > 0.0f) ? v0 : (expf(v0) - 1.0f);
                        v1 = (v1 > 0.0f) ? v1 : (expf(v1) - 1.0f);
                    }
                    size_t o;
                    if (BATCH) {
                        int tb = row >> 13, nd = row & (VT - 1);
                        o = ((size_t)(tb * NG + gg) * VT + nd) * 64 + col;
                    } else {
                        o = (size_t)gg * VH + (size_t)row * 64 + col;
                    }
                    if (EPI == 2) {
                        float2 e2 = *(const float2*)&extra[(size_t)row * 64 + col];
                        v0 = e2.x + tanhf(v0);
                        v1 = e2.y + tanhf(v1);
                    }
                    *(float2*)&out[o] = make_float2(v0, v1);
                }
            }
        }
    }
}

// ---------------- GRU gates + output ----------------
__global__ void k_gates(float* __restrict__ out, const float* __restrict__ xgt, int t) {
    int i = blockIdx.x * blockDim.x + threadIdx.x;
    float rx = xgt[i], zx = xgt[VH + i], nx = xgt[2 * VH + i];
    float hr = g_hz[i], zh = g_hz[VH + i], ho = g_ho[i];
    float r = 1.0f / (1.0f + expf(-(rx + hr)));
    float z = 1.0f / (1.0f + expf(-(zx + zh)));
    float n = tanhf(nx + r * hr);
    float h = (1.0f - z) * n + z * ho;
    g_h[i] = h;
    int node = i >> 6, c = i & 63;
    out[((size_t)node * TT + t) * HH + c] = h;
}

// ---------------- launch ----------------
extern "C" void kernel_launch(void* const* d_in, const int* in_sizes, int n_in,
                              void* d_out, int out_size) {
    const float* x     = (const float*)d_in[0];
    const float* attr  = (const float*)d_in[1];
    const float* Wk    = (const float*)d_in[2];
    const float* Wroot = (const float*)d_in[3];
    const float* bias  = (const float*)d_in[4];
    const int*   eidx  = (const int*)d_in[5];
    float*       out   = (float*)d_out;

    __half *pWt, *pFvH, *pFvX;
    float *pBias, *pH, *pA, *pHO, *pHZ, *pXG;
    cudaGetSymbolAddress((void**)&pWt,   g_WtH);
    cudaGetSymbolAddress((void**)&pFvH,  g_FvH);
    cudaGetSymbolAddress((void**)&pFvX,  g_FvX);
    cudaGetSymbolAddress((void**)&pBias, g_biasP);
    cudaGetSymbolAddress((void**)&pH,    g_h);
    cudaGetSymbolAddress((void**)&pA,    g_a);
    cudaGetSymbolAddress((void**)&pHO,   g_ho);
    cudaGetSymbolAddress((void**)&pHZ,   g_hz);
    cudaGetSymbolAddress((void**)&pXG,   g_xg);

    // smem: 4 A stages + 4 B stages (2 per half), in halfs -> bytes
    const int SM1 = (4 * 64 * 40 + 4 * 1 * 64 * 40) * 2;   // 40960
    const int SM2 = (4 * 64 * 40 + 4 * 2 * 64 * 40) * 2;   // 61440
    const int SM3 = (4 * 64 * 40 + 4 * 3 * 64 * 40) * 2;   // 81920
    cudaFuncSetAttribute(k_gemm<1, 1, 0>, cudaFuncAttributeMaxDynamicSharedMemorySize, SM1);
    cudaFuncSetAttribute(k_gemm<1, 2, 0>, cudaFuncAttributeMaxDynamicSharedMemorySize, SM1);
    cudaFuncSetAttribute(k_gemm<2, 0, 0>, cudaFuncAttributeMaxDynamicSharedMemorySize, SM2);
    cudaFuncSetAttribute(k_gemm<3, 0, 1>, cudaFuncAttributeMaxDynamicSharedMemorySize, SM3);

    k_prep<<<(NCONV * HH * KK + 255) / 256, 256>>>(Wk, Wroot, bias, attr);
    k_scan<<<1, 1024>>>(eidx);
    k_fill<<<VV / 8, 256>>>(eidx);

    const dim3 sblk(64, 4);
    const int  HK = HH * KK;
    const int  GG = VT / 64;     // 128

    // ---- x-side hoisted: scatter all 12 t, then one batched NG=3 GEMM ----
    k_scatter<<<dim3(VT / 4, TT), sblk>>>(x, TT * HH, pFvX);
    k_gemm<3, 0, 1><<<GG * TT, 256, SM3>>>(pFvX, pWt, pBias, nullptr, pXG);

    for (int t = 0; t < TT; t++) {
        // ODE: a = elu(conv5(h)) ; ho = h + tanh(conv6(a))
        k_scatter<<<VT / 4, sblk>>>(pH, HH, pFvH);
        k_gemm<1, 1, 0><<<GG, 256, SM1>>>(pFvH, pWt + 5 * HK, pBias + 5 * HH, nullptr, pA);
        k_scatter<<<VT / 4, sblk>>>(pA, HH, pFvH);
        k_gemm<1, 2, 0><<<GG, 256, SM1>>>(pFvH, pWt + 6 * HK, pBias + 6 * HH, pH, pHO);
        // GRU h-side fused: [hr | zh] = conv{1,3}(ho)
        k_scatter<<<VT / 4, sblk>>>(pHO, HH, pFvH);
        k_gemm<2, 0, 0><<<GG, 256, SM2>>>(pFvH, pWt + 3 * HK, pBias + 3 * HH, nullptr, pHZ);
        // gates + output
        k_gates<<<VH / 256, 256>>>(out, pXG + (size_t)t * 3 * VH, t);
    }
}